// round 3
// baseline (speedup 1.0000x reference)
#include <cuda_runtime.h>
#include <math.h>

#define BB   4
#define SS   2048
#define HH   16
#define DEP  64
#define DM   1024
#define MR   (BB*SS)   // 8192 rows

// Scratch (device globals: allocation-free per harness rules). 32 MB each.
__device__ float g_q[(size_t)MR*DM];
__device__ float g_k[(size_t)MR*DM];
__device__ float g_v[(size_t)MR*DM];
__device__ float g_ctx[(size_t)MR*DM];

// ---------------------------------------------------------------------------
// GEMM: C[M,N] = A[M,K] @ W[N,K]^T + bias  (K-major A and W, fp32)
// BM=128, BN=64, BK=16, 256 threads, 8x4 per-thread micro-tile.
// GATHER_A: A is read from head-split layout [(b,h),s,d] (for the dense proj)
// SPLIT_C : C is written to head-split layout [(b,h),s,d] (for Q/K/V proj)
// ---------------------------------------------------------------------------
template<bool GATHER_A, bool SPLIT_C>
__global__ void __launch_bounds__(256) gemm_kernel(const float* __restrict__ A,
                                                   const float* __restrict__ W,
                                                   const float* __restrict__ bias,
                                                   float* __restrict__ C)
{
    __shared__ float As[16][128];  // k-major (transposed on store)
    __shared__ float Ws[16][64];

    const int tid = threadIdx.x;
    const int tx = tid & 15, ty = tid >> 4;
    const int bm = blockIdx.x * 128;
    const int bn = blockIdx.y * 64;

    float acc[8][4];
#pragma unroll
    for (int i = 0; i < 8; i++)
#pragma unroll
        for (int j = 0; j < 4; j++) acc[i][j] = 0.f;

    for (int kt = 0; kt < DM; kt += 16) {
        // A tile: 128 rows x 16 k = 512 float4, 2 per thread
#pragma unroll
        for (int r = 0; r < 2; r++) {
            int f = tid + r * 256;
            int row = f >> 2, kq = f & 3;
            int m = bm + row, kk = kt + kq * 4;
            const float* src;
            if (GATHER_A) {
                int b = m >> 11, s = m & (SS - 1);
                int h = kk >> 6, d = kk & 63;
                src = &A[(((size_t)(b * HH + h)) * SS + s) * DEP + d];
            } else {
                src = &A[(size_t)m * DM + kk];
            }
            float4 v4 = *(const float4*)src;
            As[kq*4+0][row] = v4.x; As[kq*4+1][row] = v4.y;
            As[kq*4+2][row] = v4.z; As[kq*4+3][row] = v4.w;
        }
        // W tile: 64 rows x 16 k = 256 float4, 1 per thread
        {
            int row = tid >> 2, kq = tid & 3;
            float4 v4 = *(const float4*)&W[(size_t)(bn + row) * DM + kt + kq * 4];
            Ws[kq*4+0][row] = v4.x; Ws[kq*4+1][row] = v4.y;
            Ws[kq*4+2][row] = v4.z; Ws[kq*4+3][row] = v4.w;
        }
        __syncthreads();

#pragma unroll
        for (int k = 0; k < 16; k++) {
            float4 w4 = *(const float4*)&Ws[k][tx * 4];
            float4 a0 = *(const float4*)&As[k][ty * 8];
            float4 a1 = *(const float4*)&As[k][ty * 8 + 4];
            float a[8] = {a0.x, a0.y, a0.z, a0.w, a1.x, a1.y, a1.z, a1.w};
            float w[4] = {w4.x, w4.y, w4.z, w4.w};
#pragma unroll
            for (int i = 0; i < 8; i++)
#pragma unroll
                for (int j = 0; j < 4; j++)
                    acc[i][j] = fmaf(a[i], w[j], acc[i][j]);
        }
        __syncthreads();
    }

    const int n0 = bn + tx * 4;
    float4 bv = *(const float4*)&bias[n0];
#pragma unroll
    for (int i = 0; i < 8; i++) {
        int m = bm + ty * 8 + i;
        float4 o;
        o.x = acc[i][0] + bv.x; o.y = acc[i][1] + bv.y;
        o.z = acc[i][2] + bv.z; o.w = acc[i][3] + bv.w;
        if (SPLIT_C) {
            int b = m >> 11, s = m & (SS - 1);
            int h = n0 >> 6, d = n0 & 63;
            *(float4*)&C[(((size_t)(b * HH + h)) * SS + s) * DEP + d] = o;
        } else {
            *(float4*)&C[(size_t)m * DM + n0] = o;
        }
    }
}

// ---------------------------------------------------------------------------
// Flash-attention style kernel, fp32, per (b,h): 64-query tiles, loop 64-key
// tiles, online softmax. 256 threads, 4x4 per-thread micro-tile.
// Q pre-scaled by 1/sqrt(depth)=0.125 at load.
// ---------------------------------------------------------------------------
#define ATTN_SMEM ((64*68 + 64*64 + 64*64 + 64*68) * 4)

__global__ void __launch_bounds__(256) attn_kernel(const float* __restrict__ Q,
                                                   const float* __restrict__ K,
                                                   const float* __restrict__ V,
                                                   float* __restrict__ O)
{
    extern __shared__ float sm[];
    float* Qs = sm;              // [64][68] q-major (broadcast operand)
    float* Ks = Qs + 64 * 68;    // [64][64] d-major (vector operand)
    float* Vs = Ks + 64 * 64;    // [64][64] k-major (vector operand)
    float* Ps = Vs + 64 * 64;    // [64][68] q-major (broadcast operand)

    const int tid = threadIdx.x;
    const int tx = tid & 15, ty = tid >> 4;
    const int bh = blockIdx.y;
    const int q0 = blockIdx.x * 64;
    const float* Qg = Q + (size_t)bh * SS * DEP;
    const float* Kg = K + (size_t)bh * SS * DEP;
    const float* Vg = V + (size_t)bh * SS * DEP;

    // Load Q tile (scaled)
#pragma unroll
    for (int r = 0; r < 4; r++) {
        int f = tid + r * 256;
        int row = f >> 4, c4 = (f & 15) * 4;
        float4 v4 = *(const float4*)&Qg[(size_t)(q0 + row) * DEP + c4];
        v4.x *= 0.125f; v4.y *= 0.125f; v4.z *= 0.125f; v4.w *= 0.125f;
        *(float4*)&Qs[row * 68 + c4] = v4;
    }

    float mst[4], lst[4], oacc[4][4];
#pragma unroll
    for (int i = 0; i < 4; i++) {
        mst[i] = -1e30f; lst[i] = 0.f;
#pragma unroll
        for (int j = 0; j < 4; j++) oacc[i][j] = 0.f;
    }

    for (int kt = 0; kt < SS / 64; kt++) {
        __syncthreads();  // prior PV reads done before overwriting tiles
        int k0 = kt * 64;
#pragma unroll
        for (int r = 0; r < 4; r++) {
            int f = tid + r * 256;
            int n = f >> 4, dq = f & 15;
            float4 v4 = *(const float4*)&Kg[(size_t)(k0 + n) * DEP + dq * 4];
            Ks[(dq*4+0)*64 + n] = v4.x;
            Ks[(dq*4+1)*64 + n] = v4.y;
            Ks[(dq*4+2)*64 + n] = v4.z;
            Ks[(dq*4+3)*64 + n] = v4.w;
            float4 w4 = *(const float4*)&Vg[(size_t)(k0 + n) * DEP + dq * 4];
            *(float4*)&Vs[n * 64 + dq * 4] = w4;
        }
        __syncthreads();

        // S = Q K^T (already scaled)
        float sc[4][4];
#pragma unroll
        for (int i = 0; i < 4; i++)
#pragma unroll
            for (int j = 0; j < 4; j++) sc[i][j] = 0.f;

#pragma unroll 4
        for (int d = 0; d < 64; d += 4) {
            float4 a4[4], b4[4];
#pragma unroll
            for (int i = 0; i < 4; i++) a4[i] = *(const float4*)&Qs[(ty*4+i)*68 + d];
#pragma unroll
            for (int t = 0; t < 4; t++) b4[t] = *(const float4*)&Ks[(d+t)*64 + tx*4];
#pragma unroll
            for (int i = 0; i < 4; i++) {
                float av[4] = {a4[i].x, a4[i].y, a4[i].z, a4[i].w};
#pragma unroll
                for (int t = 0; t < 4; t++) {
                    sc[i][0] = fmaf(av[t], b4[t].x, sc[i][0]);
                    sc[i][1] = fmaf(av[t], b4[t].y, sc[i][1]);
                    sc[i][2] = fmaf(av[t], b4[t].z, sc[i][2]);
                    sc[i][3] = fmaf(av[t], b4[t].w, sc[i][3]);
                }
            }
        }

        // Online softmax update (row groups span 16 lanes: shfl_xor 8..1)
#pragma unroll
        for (int i = 0; i < 4; i++) {
            float mloc = fmaxf(fmaxf(sc[i][0], sc[i][1]), fmaxf(sc[i][2], sc[i][3]));
#pragma unroll
            for (int off = 8; off >= 1; off >>= 1)
                mloc = fmaxf(mloc, __shfl_xor_sync(0xffffffffu, mloc, off));
            float mnew = fmaxf(mst[i], mloc);
            float fct = __expf(mst[i] - mnew);
            mst[i] = mnew;
            float lloc = 0.f;
#pragma unroll
            for (int j = 0; j < 4; j++) {
                sc[i][j] = __expf(sc[i][j] - mnew);
                lloc += sc[i][j];
            }
#pragma unroll
            for (int off = 8; off >= 1; off >>= 1)
                lloc += __shfl_xor_sync(0xffffffffu, lloc, off);
            lst[i] = lst[i] * fct + lloc;
#pragma unroll
            for (int j = 0; j < 4; j++) oacc[i][j] *= fct;
        }

        // Stage P to smem
#pragma unroll
        for (int i = 0; i < 4; i++)
            *(float4*)&Ps[(ty*4+i)*68 + tx*4] =
                make_float4(sc[i][0], sc[i][1], sc[i][2], sc[i][3]);
        __syncthreads();

        // O += P V
#pragma unroll 4
        for (int kk = 0; kk < 64; kk += 4) {
            float4 a4[4], b4[4];
#pragma unroll
            for (int i = 0; i < 4; i++) a4[i] = *(const float4*)&Ps[(ty*4+i)*68 + kk];
#pragma unroll
            for (int t = 0; t < 4; t++) b4[t] = *(const float4*)&Vs[(kk+t)*64 + tx*4];
#pragma unroll
            for (int i = 0; i < 4; i++) {
                float av[4] = {a4[i].x, a4[i].y, a4[i].z, a4[i].w};
#pragma unroll
                for (int t = 0; t < 4; t++) {
                    oacc[i][0] = fmaf(av[t], b4[t].x, oacc[i][0]);
                    oacc[i][1] = fmaf(av[t], b4[t].y, oacc[i][1]);
                    oacc[i][2] = fmaf(av[t], b4[t].z, oacc[i][2]);
                    oacc[i][3] = fmaf(av[t], b4[t].w, oacc[i][3]);
                }
            }
        }
    }

    float* Og = O + (size_t)bh * SS * DEP;
#pragma unroll
    for (int i = 0; i < 4; i++) {
        float inv = 1.0f / lst[i];
        float4 o4 = make_float4(oacc[i][0]*inv, oacc[i][1]*inv,
                                oacc[i][2]*inv, oacc[i][3]*inv);
        *(float4*)&Og[(size_t)(q0 + ty*4 + i) * DEP + tx*4] = o4;
    }
}

// ---------------------------------------------------------------------------
extern "C" void kernel_launch(void* const* d_in, const int* in_sizes, int n_in,
                              void* d_out, int out_size)
{
    const float* query   = (const float*)d_in[0];
    const float* key     = (const float*)d_in[1];
    const float* value   = (const float*)d_in[2];
    const float* wq_w    = (const float*)d_in[3];
    const float* wq_b    = (const float*)d_in[4];
    const float* wk_w    = (const float*)d_in[5];
    const float* wk_b    = (const float*)d_in[6];
    const float* wv_w    = (const float*)d_in[7];
    const float* wv_b    = (const float*)d_in[8];
    const float* dense_w = (const float*)d_in[9];
    const float* dense_b = (const float*)d_in[10];
    float* out = (float*)d_out;

    float *qb, *kb, *vb, *cb;
    cudaGetSymbolAddress((void**)&qb, g_q);
    cudaGetSymbolAddress((void**)&kb, g_k);
    cudaGetSymbolAddress((void**)&vb, g_v);
    cudaGetSymbolAddress((void**)&cb, g_ctx);

    dim3 gg(MR / 128, DM / 64);
    gemm_kernel<false, true><<<gg, 256>>>(query, wq_w, wq_b, qb);
    gemm_kernel<false, true><<<gg, 256>>>(key,   wk_w, wk_b, kb);
    gemm_kernel<false, true><<<gg, 256>>>(value, wv_w, wv_b, vb);

    cudaFuncSetAttribute(attn_kernel,
                         cudaFuncAttributeMaxDynamicSharedMemorySize, ATTN_SMEM);
    dim3 ga(SS / 64, BB * HH);
    attn_kernel<<<ga, 256, ATTN_SMEM>>>(qb, kb, vb, cb);

    gemm_kernel<true, false><<<gg, 256>>>(cb, dense_w, dense_b, out);
}